// round 5
// baseline (speedup 1.0000x reference)
#include <cuda_runtime.h>
#include <cstdint>

#define NN 50000
#define NE 800000
#define D  256
#define BN_EPS 1e-5f
#define NSCB 196   // ceil(NN/256) scan blocks

// ---------------- scratch (static device allocations) ----------------
__device__ float g_h[NN * D];        // 51.2 MB: h = x @ W^T
__device__ float g_dinv[NN];
__device__ int   g_cnt[NN];          // degree count; consumed by fill (atomicSub)
__device__ int   g_off[NN + 1];
__device__ int   g_src[NE];
__device__ int   g_bsum[NSCB];
__device__ int   g_boff[NSCB];
__device__ float g_bnstat[2 * D];    // [0:D) colsum, [D:2D) colsumsq
__device__ float g_bn_a[D];
__device__ float g_bn_b[D];

// ---------------- count edges per target ----------------
__global__ void k_count(const int* __restrict__ ei) {
    int e = blockIdx.x * blockDim.x + threadIdx.x;
    if (e < NE) atomicAdd(&g_cnt[ei[NE + e]], 1);
}

// ---------------- multi-block exclusive scan ----------------
__device__ __forceinline__ int block_incl_scan256(int v, int tid) {
    __shared__ int ws[8];
    int lane = tid & 31, w = tid >> 5;
    int inc = v;
#pragma unroll
    for (int o = 1; o < 32; o <<= 1) {
        int n = __shfl_up_sync(0xFFFFFFFFu, inc, o);
        if (lane >= o) inc += n;
    }
    if (lane == 31) ws[w] = inc;
    __syncthreads();
    if (w == 0) {
        int s = (lane < 8) ? ws[lane] : 0;
#pragma unroll
        for (int o = 1; o < 8; o <<= 1) {
            int n = __shfl_up_sync(0xFFFFFFFFu, s, o);
            if (lane >= o) s += n;
        }
        if (lane < 8) ws[lane] = s;
    }
    __syncthreads();
    return inc + (w > 0 ? ws[w - 1] : 0);
}

// scan phase 1 + dinv
__global__ __launch_bounds__(256) void k_scan1(void) {
    int tid = threadIdx.x;
    int idx = blockIdx.x * 256 + tid;
    int v = (idx < NN) ? g_cnt[idx] : 0;
    if (idx < NN) g_dinv[idx] = rsqrtf((float)(v + 1));
    int inc = block_incl_scan256(v, tid);
    if (idx < NN) g_off[idx] = inc - v;
    if (tid == 255) g_bsum[blockIdx.x] = inc;
}

__global__ __launch_bounds__(256) void k_scan2(void) {
    int tid = threadIdx.x;
    int v = (tid < NSCB) ? g_bsum[tid] : 0;
    int inc = block_incl_scan256(v, tid);
    if (tid < NSCB) g_boff[tid] = inc - v;
}

__global__ __launch_bounds__(256) void k_scan3(void) {
    int tid = threadIdx.x;
    int idx = blockIdx.x * 256 + tid;
    if (idx < NN) g_off[idx] += g_boff[blockIdx.x];
    if (idx == 0) g_off[NN] = NE;
}

// fill CSR: consume g_cnt as cursor (order within a list is irrelevant)
__global__ void k_fill(const int* __restrict__ ei) {
    int e = blockIdx.x * blockDim.x + threadIdx.x;
    if (e < NE) {
        int r = ei[e];
        int c = ei[NE + e];
        int pos = g_off[c] + atomicSub(&g_cnt[c], 1) - 1;
        g_src[pos] = r;
    }
}

// ---------------- 3xTF32 tensor-core GEMM: H = X @ W^T ----------------
// BM=128 BN=128 BK=16, 512 threads = 16 warps (4 m-dir x 4 n-dir), warp tile 32x32.
#define GPAD 20

__device__ __forceinline__ unsigned f2tf32(float f) {
    unsigned r;
    asm("cvt.rna.tf32.f32 %0, %1;" : "=r"(r) : "f"(f));
    return r;
}

#define MMA_TF32(acc, a, b) \
    asm volatile("mma.sync.aligned.m16n8k8.row.col.f32.tf32.tf32.f32 " \
                 "{%0,%1,%2,%3},{%4,%5,%6,%7},{%8,%9},{%0,%1,%2,%3};" \
                 : "+f"(acc[0]), "+f"(acc[1]), "+f"(acc[2]), "+f"(acc[3]) \
                 : "r"(a[0]), "r"(a[1]), "r"(a[2]), "r"(a[3]), "r"(b[0]), "r"(b[1]))

__global__ __launch_bounds__(512) void k_gemm_tf32(const float* __restrict__ X,
                                                   const float* __restrict__ W,
                                                   float* __restrict__ H) {
    __shared__ unsigned Ahi[128][GPAD], Alo[128][GPAD];
    __shared__ unsigned Bhi[128][GPAD], Blo[128][GPAD];

    const int bm = blockIdx.x * 128;
    const int bn = blockIdx.y * 128;
    const int tid = threadIdx.x;
    const int warp = tid >> 5, lane = tid & 31;
    const int wm = warp >> 2, wn = warp & 3;   // 4x4 warps, warp tile 32x32
    const int grp = lane >> 2, tig = lane & 3;

    float acc[2][4][4];
#pragma unroll
    for (int mi = 0; mi < 2; mi++)
#pragma unroll
        for (int ni = 0; ni < 4; ni++)
#pragma unroll
            for (int q = 0; q < 4; q++) acc[mi][ni][q] = 0.0f;

    const int lrow = tid >> 2;
    const int lkq = (tid & 3) * 4;

    for (int k0 = 0; k0 < D; k0 += 16) {
        // A tile: 128 rows x 16 k = 512 float4, 1 per thread
        {
            float4 v = make_float4(0.f, 0.f, 0.f, 0.f);
            int gr = bm + lrow;
            if (gr < NN) v = *(const float4*)&X[(size_t)gr * D + k0 + lkq];
            unsigned h0 = f2tf32(v.x), h1 = f2tf32(v.y), h2 = f2tf32(v.z), h3 = f2tf32(v.w);
            Ahi[lrow][lkq+0] = h0; Ahi[lrow][lkq+1] = h1; Ahi[lrow][lkq+2] = h2; Ahi[lrow][lkq+3] = h3;
            Alo[lrow][lkq+0] = f2tf32(v.x - __uint_as_float(h0));
            Alo[lrow][lkq+1] = f2tf32(v.y - __uint_as_float(h1));
            Alo[lrow][lkq+2] = f2tf32(v.z - __uint_as_float(h2));
            Alo[lrow][lkq+3] = f2tf32(v.w - __uint_as_float(h3));
        }
        // B tile: 128 rows x 16 k = 512 float4, 1 per thread
        {
            float4 v = *(const float4*)&W[(size_t)(bn + lrow) * D + k0 + lkq];
            unsigned h0 = f2tf32(v.x), h1 = f2tf32(v.y), h2 = f2tf32(v.z), h3 = f2tf32(v.w);
            Bhi[lrow][lkq+0] = h0; Bhi[lrow][lkq+1] = h1; Bhi[lrow][lkq+2] = h2; Bhi[lrow][lkq+3] = h3;
            Blo[lrow][lkq+0] = f2tf32(v.x - __uint_as_float(h0));
            Blo[lrow][lkq+1] = f2tf32(v.y - __uint_as_float(h1));
            Blo[lrow][lkq+2] = f2tf32(v.z - __uint_as_float(h2));
            Blo[lrow][lkq+3] = f2tf32(v.w - __uint_as_float(h3));
        }
        __syncthreads();

#pragma unroll
        for (int ks = 0; ks < 16; ks += 8) {
            unsigned ah[2][4], al[2][4], bh[4][2], bl[4][2];
#pragma unroll
            for (int mi = 0; mi < 2; mi++) {
                int r = wm * 32 + mi * 16 + grp;
                ah[mi][0] = Ahi[r][ks+tig];     ah[mi][1] = Ahi[r+8][ks+tig];
                ah[mi][2] = Ahi[r][ks+tig+4];   ah[mi][3] = Ahi[r+8][ks+tig+4];
                al[mi][0] = Alo[r][ks+tig];     al[mi][1] = Alo[r+8][ks+tig];
                al[mi][2] = Alo[r][ks+tig+4];   al[mi][3] = Alo[r+8][ks+tig+4];
            }
#pragma unroll
            for (int ni = 0; ni < 4; ni++) {
                int c = wn * 32 + ni * 8 + grp;
                bh[ni][0] = Bhi[c][ks+tig];  bh[ni][1] = Bhi[c][ks+tig+4];
                bl[ni][0] = Blo[c][ks+tig];  bl[ni][1] = Blo[c][ks+tig+4];
            }
#pragma unroll
            for (int mi = 0; mi < 2; mi++)
#pragma unroll
                for (int ni = 0; ni < 4; ni++) {
                    MMA_TF32(acc[mi][ni], ah[mi], bh[ni]);
                    MMA_TF32(acc[mi][ni], ah[mi], bl[ni]);
                    MMA_TF32(acc[mi][ni], al[mi], bh[ni]);
                }
        }
        __syncthreads();
    }

#pragma unroll
    for (int mi = 0; mi < 2; mi++)
#pragma unroll
        for (int ni = 0; ni < 4; ni++) {
            int r0 = bm + wm * 32 + mi * 16 + grp;
            int c0 = bn + wn * 32 + ni * 8 + tig * 2;
            if (r0 < NN) {
                float2 v = make_float2(acc[mi][ni][0], acc[mi][ni][1]);
                *(float2*)&H[(size_t)r0 * D + c0] = v;
            }
            if (r0 + 8 < NN) {
                float2 v = make_float2(acc[mi][ni][2], acc[mi][ni][3]);
                *(float2*)&H[(size_t)(r0 + 8) * D + c0] = v;
            }
        }
}

// ---------------- gather: one block (256 thr) per target node ----------------
__global__ __launch_bounds__(256) void k_gather(const float* __restrict__ bias,
                                                float* __restrict__ out) {
    const int c = blockIdx.x;
    const int d = threadIdx.x;
    const float dc = g_dinv[c];
    const int beg = g_off[c];
    const int end = g_off[c + 1];
    float acc = g_h[(size_t)c * D + d] * dc;   // self loop
    int j = beg;
    for (; j + 3 < end; j += 4) {
        int r0 = __ldg(&g_src[j]);
        int r1 = __ldg(&g_src[j + 1]);
        int r2 = __ldg(&g_src[j + 2]);
        int r3 = __ldg(&g_src[j + 3]);
        float w0 = g_dinv[r0], w1 = g_dinv[r1], w2 = g_dinv[r2], w3 = g_dinv[r3];
        float v0 = g_h[(size_t)r0 * D + d];
        float v1 = g_h[(size_t)r1 * D + d];
        float v2 = g_h[(size_t)r2 * D + d];
        float v3 = g_h[(size_t)r3 * D + d];
        acc = fmaf(v0, w0, acc);
        acc = fmaf(v1, w1, acc);
        acc = fmaf(v2, w2, acc);
        acc = fmaf(v3, w3, acc);
    }
    for (; j < end; j++) {
        int r = __ldg(&g_src[j]);
        acc = fmaf(g_h[(size_t)r * D + d], g_dinv[r], acc);
    }
    out[(size_t)c * D + d] = fmaf(acc, dc, bias[d]);
}

// ---------------- BN ----------------
__global__ __launch_bounds__(256) void k_bn_stats(const float* __restrict__ out) {
    int d = threadIdx.x;
    float s = 0.f, s2 = 0.f;
    for (int row = blockIdx.x; row < NN; row += gridDim.x) {
        float v = out[(size_t)row * D + d];
        s += v;
        s2 = fmaf(v, v, s2);
    }
    atomicAdd(&g_bnstat[d], s);
    atomicAdd(&g_bnstat[D + d], s2);
}

__global__ void k_bn_params(const float* __restrict__ gamma, const float* __restrict__ beta) {
    int d = threadIdx.x;
    float inv_n = 1.0f / (float)NN;
    float mean = g_bnstat[d] * inv_n;
    float var = g_bnstat[D + d] * inv_n - mean * mean;
    float a = gamma[d] * rsqrtf(var + BN_EPS);
    g_bn_a[d] = a;
    g_bn_b[d] = beta[d] - mean * a;
}

__global__ void k_bn_apply(float* __restrict__ out) {
    int idx = blockIdx.x * blockDim.x + threadIdx.x;
    if (idx >= NN * (D / 4)) return;
    int dq = (idx & 63) * 4;
    float4 a = *(const float4*)&g_bn_a[dq];
    float4 b = *(const float4*)&g_bn_b[dq];
    float4 v = ((const float4*)out)[idx];
    float4 o;
    o.x = fmaxf(fmaf(v.x, a.x, b.x), 0.f);
    o.y = fmaxf(fmaf(v.y, a.y, b.y), 0.f);
    o.z = fmaxf(fmaf(v.z, a.z, b.z), 0.f);
    o.w = fmaxf(fmaf(v.w, a.w, b.w), 0.f);
    ((float4*)out)[idx] = o;
}

// ---------------- launch ----------------
extern "C" void kernel_launch(void* const* d_in, const int* in_sizes, int n_in,
                              void* d_out, int out_size) {
    const float* x = (const float*)d_in[0];
    const int* ei = (const int*)d_in[1];
    const float* W = (const float*)d_in[2];
    const float* bias = (const float*)d_in[3];
    const float* gamma = (const float*)d_in[4];
    const float* beta = (const float*)d_in[5];
    float* out = (float*)d_out;

    float* h;   cudaGetSymbolAddress((void**)&h, g_h);
    int* cnt;   cudaGetSymbolAddress((void**)&cnt, g_cnt);
    float* bns; cudaGetSymbolAddress((void**)&bns, g_bnstat);

    cudaMemsetAsync(cnt, 0, NN * sizeof(int));
    cudaMemsetAsync(bns, 0, 2 * D * sizeof(float));

    // kernel order chosen so the profiler window lands on k_gemm_tf32 (4th kernel)
    k_count<<<(NE + 255) / 256, 256>>>(ei);
    k_scan1<<<NSCB, 256>>>();
    k_scan2<<<1, 256>>>();

    dim3 ggrid((NN + 127) / 128, 2);
    k_gemm_tf32<<<ggrid, 512>>>(x, W, h);

    k_scan3<<<NSCB, 256>>>();
    k_fill<<<(NE + 255) / 256, 256>>>(ei);

    k_gather<<<NN, 256>>>(bias, out);

    k_bn_stats<<<512, 256>>>(out);
    k_bn_params<<<1, 256>>>(gamma, beta);

    int q = NN * (D / 4);
    k_bn_apply<<<(q + 255) / 256, 256>>>(out);
}

// round 6
// speedup vs baseline: 1.3594x; 1.3594x over previous
#include <cuda_runtime.h>
#include <cstdint>

#define NN 50000
#define NE 800000
#define D  256
#define BN_EPS 1e-5f
#define NSCB 196   // ceil(NN/256) scan blocks

// ---------------- scratch (static device allocations) ----------------
__device__ float g_h[NN * D];        // 51.2 MB: h = x @ W^T
__device__ float g_dinv[NN];
__device__ int   g_cnt[NN];          // degree count; consumed by fill (atomicSub)
__device__ int   g_off[NN + 1];
__device__ int   g_src[NE];
__device__ int   g_bsum[NSCB];
__device__ int   g_boff[NSCB];
__device__ float g_bnstat[2 * D];
__device__ float g_bn_a[D];
__device__ float g_bn_b[D];

// ---------------- count edges per target ----------------
__global__ void k_count(const int* __restrict__ ei) {
    int e = blockIdx.x * blockDim.x + threadIdx.x;
    if (e < NE) atomicAdd(&g_cnt[ei[NE + e]], 1);
}

// ---------------- multi-block exclusive scan ----------------
__device__ __forceinline__ int block_incl_scan256(int v, int tid) {
    __shared__ int ws[8];
    int lane = tid & 31, w = tid >> 5;
    int inc = v;
#pragma unroll
    for (int o = 1; o < 32; o <<= 1) {
        int n = __shfl_up_sync(0xFFFFFFFFu, inc, o);
        if (lane >= o) inc += n;
    }
    if (lane == 31) ws[w] = inc;
    __syncthreads();
    if (w == 0) {
        int s = (lane < 8) ? ws[lane] : 0;
#pragma unroll
        for (int o = 1; o < 8; o <<= 1) {
            int n = __shfl_up_sync(0xFFFFFFFFu, s, o);
            if (lane >= o) s += n;
        }
        if (lane < 8) ws[lane] = s;
    }
    __syncthreads();
    return inc + (w > 0 ? ws[w - 1] : 0);
}

__global__ __launch_bounds__(256) void k_scan1(void) {
    int tid = threadIdx.x;
    int idx = blockIdx.x * 256 + tid;
    int v = (idx < NN) ? g_cnt[idx] : 0;
    if (idx < NN) g_dinv[idx] = rsqrtf((float)(v + 1));
    int inc = block_incl_scan256(v, tid);
    if (idx < NN) g_off[idx] = inc - v;
    if (tid == 255) g_bsum[blockIdx.x] = inc;
}

__global__ __launch_bounds__(256) void k_scan2(void) {
    int tid = threadIdx.x;
    int v = (tid < NSCB) ? g_bsum[tid] : 0;
    int inc = block_incl_scan256(v, tid);
    if (tid < NSCB) g_boff[tid] = inc - v;
}

__global__ __launch_bounds__(256) void k_scan3(void) {
    int tid = threadIdx.x;
    int idx = blockIdx.x * 256 + tid;
    if (idx < NN) g_off[idx] += g_boff[blockIdx.x];
    if (idx == 0) g_off[NN] = NE;
}

__global__ void k_fill(const int* __restrict__ ei) {
    int e = blockIdx.x * blockDim.x + threadIdx.x;
    if (e < NE) {
        int r = ei[e];
        int c = ei[NE + e];
        int pos = g_off[c] + atomicSub(&g_cnt[c], 1) - 1;
        g_src[pos] = r;
    }
}

// ---------------- 3xBF16 split tensor-core GEMM: H = X @ W^T ----------------
// BM=128 BN=64 BK=32, 256 threads = 8 warps (4 m x 2 n), warp tile 32x32.
// mma.sync.aligned.m16n8k16.row.col.f32.bf16.bf16.f32
// smem holds bf16x2 k-pairs: 16 pair-cols per row, padded to GPAD=20 (conflict-free).
#define GPAD 20

// pack (lo_k, hi_k) floats -> bf16x2 (k0 in low half, k1 in high half)
__device__ __forceinline__ unsigned pack_bf16x2(float k0, float k1) {
    unsigned r;
    asm("cvt.rn.bf16x2.f32 %0, %1, %2;" : "=r"(r) : "f"(k1), "f"(k0));
    return r;
}

#define MMA_BF16(acc, a, b) \
    asm volatile("mma.sync.aligned.m16n8k16.row.col.f32.bf16.bf16.f32 " \
                 "{%0,%1,%2,%3},{%4,%5,%6,%7},{%8,%9},{%0,%1,%2,%3};" \
                 : "+f"(acc[0]), "+f"(acc[1]), "+f"(acc[2]), "+f"(acc[3]) \
                 : "r"(a[0]), "r"(a[1]), "r"(a[2]), "r"(a[3]), "r"(b[0]), "r"(b[1]))

__global__ __launch_bounds__(256) void k_gemm_bf16(const float* __restrict__ X,
                                                   const float* __restrict__ W,
                                                   float* __restrict__ H) {
    __shared__ unsigned Ahi[128][GPAD], Alo[128][GPAD];
    __shared__ unsigned Bhi[64][GPAD],  Blo[64][GPAD];

    const int bm = blockIdx.x * 128;
    const int bn = blockIdx.y * 64;
    const int tid = threadIdx.x;
    const int warp = tid >> 5, lane = tid & 31;
    const int wm = warp & 3, wn = warp >> 2;       // 4x2 warps, warp tile 32x32
    const int grp = lane >> 2, tig = lane & 3;

    float acc[2][4][4];
#pragma unroll
    for (int mi = 0; mi < 2; mi++)
#pragma unroll
        for (int ni = 0; ni < 4; ni++)
#pragma unroll
            for (int q = 0; q < 4; q++) acc[mi][ni][q] = 0.0f;

    for (int k0 = 0; k0 < D; k0 += 32) {
        // A tile: 128 rows x 32 k = 1024 float4 -> 4 per thread
#pragma unroll
        for (int p = 0; p < 4; p++) {
            int f = tid + p * 256;
            int row = f >> 3;          // 8 float4 per 32-float row
            int q = f & 7;             // float4 index within row
            float4 v = make_float4(0.f, 0.f, 0.f, 0.f);
            int gr = bm + row;
            if (gr < NN) v = *(const float4*)&X[(size_t)gr * D + k0 + q * 4];
            unsigned hp0 = pack_bf16x2(v.x, v.y);
            unsigned hp1 = pack_bf16x2(v.z, v.w);
            float lx = v.x - __uint_as_float(hp0 << 16);
            float ly = v.y - __uint_as_float(hp0 & 0xFFFF0000u);
            float lz = v.z - __uint_as_float(hp1 << 16);
            float lw = v.w - __uint_as_float(hp1 & 0xFFFF0000u);
            Ahi[row][q * 2]     = hp0;
            Ahi[row][q * 2 + 1] = hp1;
            Alo[row][q * 2]     = pack_bf16x2(lx, ly);
            Alo[row][q * 2 + 1] = pack_bf16x2(lz, lw);
        }
        // B tile: 64 rows x 32 k = 512 float4 -> 2 per thread
#pragma unroll
        for (int p = 0; p < 2; p++) {
            int f = tid + p * 256;
            int row = f >> 3;
            int q = f & 7;
            float4 v = *(const float4*)&W[(size_t)(bn + row) * D + k0 + q * 4];
            unsigned hp0 = pack_bf16x2(v.x, v.y);
            unsigned hp1 = pack_bf16x2(v.z, v.w);
            float lx = v.x - __uint_as_float(hp0 << 16);
            float ly = v.y - __uint_as_float(hp0 & 0xFFFF0000u);
            float lz = v.z - __uint_as_float(hp1 << 16);
            float lw = v.w - __uint_as_float(hp1 & 0xFFFF0000u);
            Bhi[row][q * 2]     = hp0;
            Bhi[row][q * 2 + 1] = hp1;
            Blo[row][q * 2]     = pack_bf16x2(lx, ly);
            Blo[row][q * 2 + 1] = pack_bf16x2(lz, lw);
        }
        __syncthreads();

        // two k16 steps per tile: pair-col offsets 0 and 8
#pragma unroll
        for (int ks = 0; ks < 16; ks += 8) {
            unsigned ah[2][4], al[2][4], bh[4][2], bl[4][2];
#pragma unroll
            for (int mi = 0; mi < 2; mi++) {
                int r = wm * 32 + mi * 16 + grp;
                ah[mi][0] = Ahi[r][ks+tig];     ah[mi][1] = Ahi[r+8][ks+tig];
                ah[mi][2] = Ahi[r][ks+tig+4];   ah[mi][3] = Ahi[r+8][ks+tig+4];
                al[mi][0] = Alo[r][ks+tig];     al[mi][1] = Alo[r+8][ks+tig];
                al[mi][2] = Alo[r][ks+tig+4];   al[mi][3] = Alo[r+8][ks+tig+4];
            }
#pragma unroll
            for (int ni = 0; ni < 4; ni++) {
                int c = wn * 32 + ni * 8 + grp;
                bh[ni][0] = Bhi[c][ks+tig];  bh[ni][1] = Bhi[c][ks+tig+4];
                bl[ni][0] = Blo[c][ks+tig];  bl[ni][1] = Blo[c][ks+tig+4];
            }
#pragma unroll
            for (int mi = 0; mi < 2; mi++)
#pragma unroll
                for (int ni = 0; ni < 4; ni++) {
                    MMA_BF16(acc[mi][ni], ah[mi], bh[ni]);
                    MMA_BF16(acc[mi][ni], ah[mi], bl[ni]);
                    MMA_BF16(acc[mi][ni], al[mi], bh[ni]);
                }
        }
        __syncthreads();
    }

#pragma unroll
    for (int mi = 0; mi < 2; mi++)
#pragma unroll
        for (int ni = 0; ni < 4; ni++) {
            int r0 = bm + wm * 32 + mi * 16 + grp;
            int c0 = bn + wn * 32 + ni * 8 + tig * 2;
            if (r0 < NN) {
                float2 v = make_float2(acc[mi][ni][0], acc[mi][ni][1]);
                *(float2*)&H[(size_t)r0 * D + c0] = v;
            }
            if (r0 + 8 < NN) {
                float2 v = make_float2(acc[mi][ni][2], acc[mi][ni][3]);
                *(float2*)&H[(size_t)(r0 + 8) * D + c0] = v;
            }
        }
}

// ---------------- gather: one block (256 thr) per target node ----------------
__global__ __launch_bounds__(256) void k_gather(const float* __restrict__ bias,
                                                float* __restrict__ out) {
    const int c = blockIdx.x;
    const int d = threadIdx.x;
    const float dc = g_dinv[c];
    const int beg = g_off[c];
    const int end = g_off[c + 1];
    float acc = g_h[(size_t)c * D + d] * dc;   // self loop
    int j = beg;
    for (; j + 3 < end; j += 4) {
        int r0 = __ldg(&g_src[j]);
        int r1 = __ldg(&g_src[j + 1]);
        int r2 = __ldg(&g_src[j + 2]);
        int r3 = __ldg(&g_src[j + 3]);
        float w0 = g_dinv[r0], w1 = g_dinv[r1], w2 = g_dinv[r2], w3 = g_dinv[r3];
        float v0 = g_h[(size_t)r0 * D + d];
        float v1 = g_h[(size_t)r1 * D + d];
        float v2 = g_h[(size_t)r2 * D + d];
        float v3 = g_h[(size_t)r3 * D + d];
        acc = fmaf(v0, w0, acc);
        acc = fmaf(v1, w1, acc);
        acc = fmaf(v2, w2, acc);
        acc = fmaf(v3, w3, acc);
    }
    for (; j < end; j++) {
        int r = __ldg(&g_src[j]);
        acc = fmaf(g_h[(size_t)r * D + d], g_dinv[r], acc);
    }
    out[(size_t)c * D + d] = fmaf(acc, dc, bias[d]);
}

// ---------------- BN ----------------
__global__ __launch_bounds__(256) void k_bn_stats(const float* __restrict__ out) {
    int d = threadIdx.x;
    float s = 0.f, s2 = 0.f;
    for (int row = blockIdx.x; row < NN; row += gridDim.x) {
        float v = out[(size_t)row * D + d];
        s += v;
        s2 = fmaf(v, v, s2);
    }
    atomicAdd(&g_bnstat[d], s);
    atomicAdd(&g_bnstat[D + d], s2);
}

__global__ void k_bn_params(const float* __restrict__ gamma, const float* __restrict__ beta) {
    int d = threadIdx.x;
    float inv_n = 1.0f / (float)NN;
    float mean = g_bnstat[d] * inv_n;
    float var = g_bnstat[D + d] * inv_n - mean * mean;
    float a = gamma[d] * rsqrtf(var + BN_EPS);
    g_bn_a[d] = a;
    g_bn_b[d] = beta[d] - mean * a;
}

__global__ void k_bn_apply(float* __restrict__ out) {
    int idx = blockIdx.x * blockDim.x + threadIdx.x;
    if (idx >= NN * (D / 4)) return;
    int dq = (idx & 63) * 4;
    float4 a = *(const float4*)&g_bn_a[dq];
    float4 b = *(const float4*)&g_bn_b[dq];
    float4 v = ((const float4*)out)[idx];
    float4 o;
    o.x = fmaxf(fmaf(v.x, a.x, b.x), 0.f);
    o.y = fmaxf(fmaf(v.y, a.y, b.y), 0.f);
    o.z = fmaxf(fmaf(v.z, a.z, b.z), 0.f);
    o.w = fmaxf(fmaf(v.w, a.w, b.w), 0.f);
    ((float4*)out)[idx] = o;
}

// ---------------- launch ----------------
extern "C" void kernel_launch(void* const* d_in, const int* in_sizes, int n_in,
                              void* d_out, int out_size) {
    const float* x = (const float*)d_in[0];
    const int* ei = (const int*)d_in[1];
    const float* W = (const float*)d_in[2];
    const float* bias = (const float*)d_in[3];
    const float* gamma = (const float*)d_in[4];
    const float* beta = (const float*)d_in[5];
    float* out = (float*)d_out;

    float* h;   cudaGetSymbolAddress((void**)&h, g_h);
    int* cnt;   cudaGetSymbolAddress((void**)&cnt, g_cnt);
    float* bns; cudaGetSymbolAddress((void**)&bns, g_bnstat);

    cudaMemsetAsync(cnt, 0, NN * sizeof(int));
    cudaMemsetAsync(bns, 0, 2 * D * sizeof(float));

    // kernel order keeps k_gemm_bf16 in the profiler's capture slot (4th kernel)
    k_count<<<(NE + 255) / 256, 256>>>(ei);
    k_scan1<<<NSCB, 256>>>();
    k_scan2<<<1, 256>>>();

    dim3 ggrid((NN + 127) / 128, D / 64);
    k_gemm_bf16<<<ggrid, 256>>>(x, W, h);

    k_scan3<<<NSCB, 256>>>();
    k_fill<<<(NE + 255) / 256, 256>>>(ei);

    k_gather<<<NN, 256>>>(bias, out);

    k_bn_stats<<<512, 256>>>(out);
    k_bn_params<<<1, 256>>>(gamma, beta);

    int q = NN * (D / 4);
    k_bn_apply<<<(q + 255) / 256, 256>>>(out);
}

// round 7
// speedup vs baseline: 1.6345x; 1.2024x over previous
#include <cuda_runtime.h>
#include <cuda_fp16.h>
#include <cstdint>

#define NN 50000
#define NE 800000
#define D  256
#define BN_EPS 1e-5f
#define NSCB 196   // ceil(NN/256) scan blocks

// ---------------- scratch (static device allocations) ----------------
__device__ __half g_h[NN * D];       // 25.6 MB: h = x @ W^T in fp16
__device__ float g_dinv[NN];
__device__ int   g_cnt[NN];          // degree count; consumed by fill (atomicSub)
__device__ int   g_off[NN + 1];      // local-exclusive offsets (pre-boff)
__device__ int   g_src[NE];
__device__ int   g_bsum[NSCB];
__device__ int   g_boff[NSCB];
__device__ float g_bnstat[2 * D];    // [0:D) colsum, [D:2D) colsumsq
__device__ float g_bn_a[D];
__device__ float g_bn_b[D];

// ---------------- count edges per target ----------------
__global__ void k_count(const int* __restrict__ ei) {
    int e = blockIdx.x * blockDim.x + threadIdx.x;
    if (e < NE) atomicAdd(&g_cnt[ei[NE + e]], 1);
}

// ---------------- multi-block scan ----------------
__device__ __forceinline__ int block_incl_scan256(int v, int tid) {
    __shared__ int ws[8];
    int lane = tid & 31, w = tid >> 5;
    int inc = v;
#pragma unroll
    for (int o = 1; o < 32; o <<= 1) {
        int n = __shfl_up_sync(0xFFFFFFFFu, inc, o);
        if (lane >= o) inc += n;
    }
    if (lane == 31) ws[w] = inc;
    __syncthreads();
    if (w == 0) {
        int s = (lane < 8) ? ws[lane] : 0;
#pragma unroll
        for (int o = 1; o < 8; o <<= 1) {
            int n = __shfl_up_sync(0xFFFFFFFFu, s, o);
            if (lane >= o) s += n;
        }
        if (lane < 8) ws[lane] = s;
    }
    __syncthreads();
    return inc + (w > 0 ? ws[w - 1] : 0);
}

__global__ __launch_bounds__(256) void k_scan1(void) {
    int tid = threadIdx.x;
    int idx = blockIdx.x * 256 + tid;
    int v = (idx < NN) ? g_cnt[idx] : 0;
    if (idx < NN) g_dinv[idx] = rsqrtf((float)(v + 1));
    int inc = block_incl_scan256(v, tid);
    if (idx < NN) g_off[idx] = inc - v;
    if (tid == 255) g_bsum[blockIdx.x] = inc;
}

__global__ __launch_bounds__(256) void k_scan2(void) {
    int tid = threadIdx.x;
    int v = (tid < NSCB) ? g_bsum[tid] : 0;
    int inc = block_incl_scan256(v, tid);
    if (tid < NSCB) g_boff[tid] = inc - v;
}

// fill CSR: offsets = local off + block off; g_cnt consumed as cursor
__global__ void k_fill(const int* __restrict__ ei) {
    int e = blockIdx.x * blockDim.x + threadIdx.x;
    if (e < NE) {
        int r = ei[e];
        int c = ei[NE + e];
        int pos = g_off[c] + g_boff[c >> 8] + atomicSub(&g_cnt[c], 1) - 1;
        g_src[pos] = r;
    }
}

// ---------------- 3xBF16 split tensor-core GEMM: H(fp16) = X @ W^T ----------------
// BM=128 BN=64 BK=32, 256 threads = 8 warps (4m x 2n), warp tile 32x32.
#define GPAD 20

__device__ __forceinline__ unsigned pack_bf16x2(float k0, float k1) {
    unsigned r;
    asm("cvt.rn.bf16x2.f32 %0, %1, %2;" : "=r"(r) : "f"(k1), "f"(k0));
    return r;
}

#define MMA_BF16(acc, a, b) \
    asm volatile("mma.sync.aligned.m16n8k16.row.col.f32.bf16.bf16.f32 " \
                 "{%0,%1,%2,%3},{%4,%5,%6,%7},{%8,%9},{%0,%1,%2,%3};" \
                 : "+f"(acc[0]), "+f"(acc[1]), "+f"(acc[2]), "+f"(acc[3]) \
                 : "r"(a[0]), "r"(a[1]), "r"(a[2]), "r"(a[3]), "r"(b[0]), "r"(b[1]))

__global__ __launch_bounds__(256) void k_gemm_bf16(const float* __restrict__ X,
                                                   const float* __restrict__ W,
                                                   __half* __restrict__ H) {
    __shared__ unsigned Ahi[128][GPAD], Alo[128][GPAD];
    __shared__ unsigned Bhi[64][GPAD],  Blo[64][GPAD];

    const int bm = blockIdx.x * 128;
    const int bn = blockIdx.y * 64;
    const int tid = threadIdx.x;
    const int warp = tid >> 5, lane = tid & 31;
    const int wm = warp & 3, wn = warp >> 2;
    const int grp = lane >> 2, tig = lane & 3;

    float acc[2][4][4];
#pragma unroll
    for (int mi = 0; mi < 2; mi++)
#pragma unroll
        for (int ni = 0; ni < 4; ni++)
#pragma unroll
            for (int q = 0; q < 4; q++) acc[mi][ni][q] = 0.0f;

    for (int k0 = 0; k0 < D; k0 += 32) {
#pragma unroll
        for (int p = 0; p < 4; p++) {
            int f = tid + p * 256;
            int row = f >> 3;
            int q = f & 7;
            float4 v = make_float4(0.f, 0.f, 0.f, 0.f);
            int gr = bm + row;
            if (gr < NN) v = *(const float4*)&X[(size_t)gr * D + k0 + q * 4];
            unsigned hp0 = pack_bf16x2(v.x, v.y);
            unsigned hp1 = pack_bf16x2(v.z, v.w);
            float lx = v.x - __uint_as_float(hp0 << 16);
            float ly = v.y - __uint_as_float(hp0 & 0xFFFF0000u);
            float lz = v.z - __uint_as_float(hp1 << 16);
            float lw = v.w - __uint_as_float(hp1 & 0xFFFF0000u);
            Ahi[row][q * 2]     = hp0;
            Ahi[row][q * 2 + 1] = hp1;
            Alo[row][q * 2]     = pack_bf16x2(lx, ly);
            Alo[row][q * 2 + 1] = pack_bf16x2(lz, lw);
        }
#pragma unroll
        for (int p = 0; p < 2; p++) {
            int f = tid + p * 256;
            int row = f >> 3;
            int q = f & 7;
            float4 v = *(const float4*)&W[(size_t)(bn + row) * D + k0 + q * 4];
            unsigned hp0 = pack_bf16x2(v.x, v.y);
            unsigned hp1 = pack_bf16x2(v.z, v.w);
            float lx = v.x - __uint_as_float(hp0 << 16);
            float ly = v.y - __uint_as_float(hp0 & 0xFFFF0000u);
            float lz = v.z - __uint_as_float(hp1 << 16);
            float lw = v.w - __uint_as_float(hp1 & 0xFFFF0000u);
            Bhi[row][q * 2]     = hp0;
            Bhi[row][q * 2 + 1] = hp1;
            Blo[row][q * 2]     = pack_bf16x2(lx, ly);
            Blo[row][q * 2 + 1] = pack_bf16x2(lz, lw);
        }
        __syncthreads();

#pragma unroll
        for (int ks = 0; ks < 16; ks += 8) {
            unsigned ah[2][4], al[2][4], bh[4][2], bl[4][2];
#pragma unroll
            for (int mi = 0; mi < 2; mi++) {
                int r = wm * 32 + mi * 16 + grp;
                ah[mi][0] = Ahi[r][ks+tig];     ah[mi][1] = Ahi[r+8][ks+tig];
                ah[mi][2] = Ahi[r][ks+tig+4];   ah[mi][3] = Ahi[r+8][ks+tig+4];
                al[mi][0] = Alo[r][ks+tig];     al[mi][1] = Alo[r+8][ks+tig];
                al[mi][2] = Alo[r][ks+tig+4];   al[mi][3] = Alo[r+8][ks+tig+4];
            }
#pragma unroll
            for (int ni = 0; ni < 4; ni++) {
                int c = wn * 32 + ni * 8 + grp;
                bh[ni][0] = Bhi[c][ks+tig];  bh[ni][1] = Bhi[c][ks+tig+4];
                bl[ni][0] = Blo[c][ks+tig];  bl[ni][1] = Blo[c][ks+tig+4];
            }
#pragma unroll
            for (int mi = 0; mi < 2; mi++)
#pragma unroll
                for (int ni = 0; ni < 4; ni++) {
                    MMA_BF16(acc[mi][ni], ah[mi], bh[ni]);
                    MMA_BF16(acc[mi][ni], ah[mi], bl[ni]);
                    MMA_BF16(acc[mi][ni], al[mi], bh[ni]);
                }
        }
        __syncthreads();
    }

#pragma unroll
    for (int mi = 0; mi < 2; mi++)
#pragma unroll
        for (int ni = 0; ni < 4; ni++) {
            int r0 = bm + wm * 32 + mi * 16 + grp;
            int c0 = bn + wn * 32 + ni * 8 + tig * 2;
            if (r0 < NN)
                *(__half2*)&H[(size_t)r0 * D + c0] = __floats2half2_rn(acc[mi][ni][0], acc[mi][ni][1]);
            if (r0 + 8 < NN)
                *(__half2*)&H[(size_t)(r0 + 8) * D + c0] = __floats2half2_rn(acc[mi][ni][2], acc[mi][ni][3]);
        }
}

// ---------------- fused gather + bias + BN-stats ----------------
// 128 threads: thread d handles column pair (2d, 2d+1); grid-stride over nodes.
__global__ __launch_bounds__(128) void k_gather_bn(const float* __restrict__ bias,
                                                   float* __restrict__ out) {
    const int d = threadIdx.x;
    const __half2* __restrict__ H2 = (const __half2*)g_h;
    const float2 bi = *(const float2*)&bias[2 * d];
    float s0 = 0.f, s1 = 0.f, q0 = 0.f, q1 = 0.f;

    for (int c = blockIdx.x; c < NN; c += gridDim.x) {
        const float dc = g_dinv[c];
        const int beg = g_off[c] + g_boff[c >> 8];
        const int end = (c + 1 < NN) ? g_off[c + 1] + g_boff[(c + 1) >> 8] : NE;

        float2 hs = __half22float2(H2[(size_t)c * 128 + d]);
        float a0 = hs.x * dc, a1 = hs.y * dc;   // self loop

        int j = beg;
        for (; j + 3 < end; j += 4) {
            int r0 = __ldg(&g_src[j]);
            int r1 = __ldg(&g_src[j + 1]);
            int r2 = __ldg(&g_src[j + 2]);
            int r3 = __ldg(&g_src[j + 3]);
            float w0 = g_dinv[r0], w1 = g_dinv[r1], w2 = g_dinv[r2], w3 = g_dinv[r3];
            float2 v0 = __half22float2(H2[(size_t)r0 * 128 + d]);
            float2 v1 = __half22float2(H2[(size_t)r1 * 128 + d]);
            float2 v2 = __half22float2(H2[(size_t)r2 * 128 + d]);
            float2 v3 = __half22float2(H2[(size_t)r3 * 128 + d]);
            a0 = fmaf(v0.x, w0, a0); a1 = fmaf(v0.y, w0, a1);
            a0 = fmaf(v1.x, w1, a0); a1 = fmaf(v1.y, w1, a1);
            a0 = fmaf(v2.x, w2, a0); a1 = fmaf(v2.y, w2, a1);
            a0 = fmaf(v3.x, w3, a0); a1 = fmaf(v3.y, w3, a1);
        }
        for (; j < end; j++) {
            int r = __ldg(&g_src[j]);
            float w = g_dinv[r];
            float2 v = __half22float2(H2[(size_t)r * 128 + d]);
            a0 = fmaf(v.x, w, a0); a1 = fmaf(v.y, w, a1);
        }
        float o0 = fmaf(a0, dc, bi.x);
        float o1 = fmaf(a1, dc, bi.y);
        *(float2*)&out[(size_t)c * D + 2 * d] = make_float2(o0, o1);
        s0 += o0; s1 += o1;
        q0 = fmaf(o0, o0, q0); q1 = fmaf(o1, o1, q1);
    }
    atomicAdd(&g_bnstat[2 * d], s0);
    atomicAdd(&g_bnstat[2 * d + 1], s1);
    atomicAdd(&g_bnstat[D + 2 * d], q0);
    atomicAdd(&g_bnstat[D + 2 * d + 1], q1);
}

// ---------------- BN finalize ----------------
__global__ void k_bn_params(const float* __restrict__ gamma, const float* __restrict__ beta) {
    int d = threadIdx.x;
    float inv_n = 1.0f / (float)NN;
    float mean = g_bnstat[d] * inv_n;
    float var = g_bnstat[D + d] * inv_n - mean * mean;
    float a = gamma[d] * rsqrtf(var + BN_EPS);
    g_bn_a[d] = a;
    g_bn_b[d] = beta[d] - mean * a;
}

__global__ void k_bn_apply(float* __restrict__ out) {
    int idx = blockIdx.x * blockDim.x + threadIdx.x;
    if (idx >= NN * (D / 4)) return;
    int dq = (idx & 63) * 4;
    float4 a = *(const float4*)&g_bn_a[dq];
    float4 b = *(const float4*)&g_bn_b[dq];
    float4 v = ((const float4*)out)[idx];
    float4 o;
    o.x = fmaxf(fmaf(v.x, a.x, b.x), 0.f);
    o.y = fmaxf(fmaf(v.y, a.y, b.y), 0.f);
    o.z = fmaxf(fmaf(v.z, a.z, b.z), 0.f);
    o.w = fmaxf(fmaf(v.w, a.w, b.w), 0.f);
    ((float4*)out)[idx] = o;
}

// ---------------- launch ----------------
extern "C" void kernel_launch(void* const* d_in, const int* in_sizes, int n_in,
                              void* d_out, int out_size) {
    const float* x = (const float*)d_in[0];
    const int* ei = (const int*)d_in[1];
    const float* W = (const float*)d_in[2];
    const float* bias = (const float*)d_in[3];
    const float* gamma = (const float*)d_in[4];
    const float* beta = (const float*)d_in[5];
    float* out = (float*)d_out;

    __half* h;  cudaGetSymbolAddress((void**)&h, g_h);
    int* cnt;   cudaGetSymbolAddress((void**)&cnt, g_cnt);
    float* bns; cudaGetSymbolAddress((void**)&bns, g_bnstat);

    cudaMemsetAsync(cnt, 0, NN * sizeof(int));
    cudaMemsetAsync(bns, 0, 2 * D * sizeof(float));

    // order keeps k_gemm_bf16 in the profiler's capture slot (4th kernel)
    k_count<<<(NE + 255) / 256, 256>>>(ei);
    k_scan1<<<NSCB, 256>>>();
    k_scan2<<<1, 256>>>();

    dim3 ggrid((NN + 127) / 128, D / 64);
    k_gemm_bf16<<<ggrid, 256>>>(x, W, h);

    k_fill<<<(NE + 255) / 256, 256>>>(ei);

    k_gather_bn<<<1480, 128>>>(bias, out);

    k_bn_params<<<1, 256>>>(gamma, beta);

    int q = NN * (D / 4);
    k_bn_apply<<<(q + 255) / 256, 256>>>(out);
}

// round 8
// speedup vs baseline: 1.6634x; 1.0176x over previous
#include <cuda_runtime.h>
#include <cuda_fp16.h>
#include <cstdint>

#define NN 50000
#define NE 800000
#define D  256
#define BN_EPS 1e-5f
#define NSCB 196   // ceil(NN/256) scan blocks

// ---------------- scratch (static device allocations) ----------------
__device__ __half g_h[NN * D];       // 25.6 MB: h = x @ W^T in fp16
__device__ float g_dinv[NN];
__device__ int   g_cnt[NN];
__device__ int   g_off[NN + 1];      // local-exclusive offsets (pre-boff)
__device__ int   g_src[NE];
__device__ int   g_bsum[NSCB];
__device__ int   g_boff[NSCB];
__device__ float g_bnstat[2 * D];
__device__ float g_bn_a[D];
__device__ float g_bn_b[D];

// ---------------- count edges per target ----------------
__global__ void k_count(const int* __restrict__ ei) {
    int e = blockIdx.x * blockDim.x + threadIdx.x;
    if (e < NE) atomicAdd(&g_cnt[ei[NE + e]], 1);
}

// ---------------- multi-block scan ----------------
__device__ __forceinline__ int block_incl_scan256(int v, int tid) {
    __shared__ int ws[8];
    int lane = tid & 31, w = tid >> 5;
    int inc = v;
#pragma unroll
    for (int o = 1; o < 32; o <<= 1) {
        int n = __shfl_up_sync(0xFFFFFFFFu, inc, o);
        if (lane >= o) inc += n;
    }
    if (lane == 31) ws[w] = inc;
    __syncthreads();
    if (w == 0) {
        int s = (lane < 8) ? ws[lane] : 0;
#pragma unroll
        for (int o = 1; o < 8; o <<= 1) {
            int n = __shfl_up_sync(0xFFFFFFFFu, s, o);
            if (lane >= o) s += n;
        }
        if (lane < 8) ws[lane] = s;
    }
    __syncthreads();
    return inc + (w > 0 ? ws[w - 1] : 0);
}

__global__ __launch_bounds__(256) void k_scan1(void) {
    int tid = threadIdx.x;
    int idx = blockIdx.x * 256 + tid;
    int v = (idx < NN) ? g_cnt[idx] : 0;
    if (idx < NN) g_dinv[idx] = rsqrtf((float)(v + 1));
    int inc = block_incl_scan256(v, tid);
    if (idx < NN) g_off[idx] = inc - v;
    if (tid == 255) g_bsum[blockIdx.x] = inc;
}

__global__ __launch_bounds__(256) void k_scan2(void) {
    int tid = threadIdx.x;
    int v = (tid < NSCB) ? g_bsum[tid] : 0;
    int inc = block_incl_scan256(v, tid);
    if (tid < NSCB) g_boff[tid] = inc - v;
}

__global__ void k_fill(const int* __restrict__ ei) {
    int e = blockIdx.x * blockDim.x + threadIdx.x;
    if (e < NE) {
        int r = ei[e];
        int c = ei[NE + e];
        int pos = g_off[c] + g_boff[c >> 8] + atomicSub(&g_cnt[c], 1) - 1;
        g_src[pos] = r;
    }
}

// ---------------- 3xBF16 split tensor-core GEMM (ldmatrix feeding) ----------------
// BM=128 BN=64 BK=32, 256 threads = 8 warps (4m x 2n), warp tile 32x32.
#define GPAD 20

__device__ __forceinline__ unsigned pack_bf16x2(float k0, float k1) {
    unsigned r;
    asm("cvt.rn.bf16x2.f32 %0, %1, %2;" : "=r"(r) : "f"(k1), "f"(k0));
    return r;
}

#define MMA_BF16(acc, a, b) \
    asm volatile("mma.sync.aligned.m16n8k16.row.col.f32.bf16.bf16.f32 " \
                 "{%0,%1,%2,%3},{%4,%5,%6,%7},{%8,%9},{%0,%1,%2,%3};" \
                 : "+f"(acc[0]), "+f"(acc[1]), "+f"(acc[2]), "+f"(acc[3]) \
                 : "r"(a[0]), "r"(a[1]), "r"(a[2]), "r"(a[3]), "r"(b[0]), "r"(b[1]))

#define LDSM4(r, addr) \
    asm volatile("ldmatrix.sync.aligned.m8n8.x4.shared.b16 {%0,%1,%2,%3}, [%4];" \
                 : "=r"(r[0]), "=r"(r[1]), "=r"(r[2]), "=r"(r[3]) : "r"(addr))

__global__ __launch_bounds__(256) void k_gemm_bf16(const float* __restrict__ X,
                                                   const float* __restrict__ W,
                                                   __half* __restrict__ H) {
    __shared__ unsigned Ahi[128][GPAD], Alo[128][GPAD];
    __shared__ unsigned Bhi[64][GPAD],  Blo[64][GPAD];

    const int bm = blockIdx.x * 128;
    const int bn = blockIdx.y * 64;
    const int tid = threadIdx.x;
    const int warp = tid >> 5, lane = tid & 31;
    const int wm = warp & 3, wn = warp >> 2;
    const int grp = lane >> 2, tig = lane & 3;

    // ldmatrix per-lane tile addressing
    const int lr = lane & 7, sel = lane >> 3;
    const int a_row = ((sel & 1) ? 8 : 0) + lr;   // + wm*32 + mi*16
    const int a_col = (sel & 2) ? 4 : 0;          // + ks
    const int b_row = ((sel & 2) ? 8 : 0) + lr;   // + wn*32 + p*16
    const int b_col = (sel & 1) ? 4 : 0;          // + ks

    const uint32_t sAhi = (uint32_t)__cvta_generic_to_shared(&Ahi[0][0]);
    const uint32_t sAlo = (uint32_t)__cvta_generic_to_shared(&Alo[0][0]);
    const uint32_t sBhi = (uint32_t)__cvta_generic_to_shared(&Bhi[0][0]);
    const uint32_t sBlo = (uint32_t)__cvta_generic_to_shared(&Blo[0][0]);

    float acc[2][4][4];
#pragma unroll
    for (int mi = 0; mi < 2; mi++)
#pragma unroll
        for (int ni = 0; ni < 4; ni++)
#pragma unroll
            for (int q = 0; q < 4; q++) acc[mi][ni][q] = 0.0f;

    for (int k0 = 0; k0 < D; k0 += 32) {
#pragma unroll
        for (int p = 0; p < 4; p++) {
            int f = tid + p * 256;
            int row = f >> 3;
            int q = f & 7;
            float4 v = make_float4(0.f, 0.f, 0.f, 0.f);
            int gr = bm + row;
            if (gr < NN) v = *(const float4*)&X[(size_t)gr * D + k0 + q * 4];
            unsigned hp0 = pack_bf16x2(v.x, v.y);
            unsigned hp1 = pack_bf16x2(v.z, v.w);
            float lx = v.x - __uint_as_float(hp0 << 16);
            float ly = v.y - __uint_as_float(hp0 & 0xFFFF0000u);
            float lz = v.z - __uint_as_float(hp1 << 16);
            float lw = v.w - __uint_as_float(hp1 & 0xFFFF0000u);
            Ahi[row][q * 2]     = hp0;
            Ahi[row][q * 2 + 1] = hp1;
            Alo[row][q * 2]     = pack_bf16x2(lx, ly);
            Alo[row][q * 2 + 1] = pack_bf16x2(lz, lw);
        }
#pragma unroll
        for (int p = 0; p < 2; p++) {
            int f = tid + p * 256;
            int row = f >> 3;
            int q = f & 7;
            float4 v = *(const float4*)&W[(size_t)(bn + row) * D + k0 + q * 4];
            unsigned hp0 = pack_bf16x2(v.x, v.y);
            unsigned hp1 = pack_bf16x2(v.z, v.w);
            float lx = v.x - __uint_as_float(hp0 << 16);
            float ly = v.y - __uint_as_float(hp0 & 0xFFFF0000u);
            float lz = v.z - __uint_as_float(hp1 << 16);
            float lw = v.w - __uint_as_float(hp1 & 0xFFFF0000u);
            Bhi[row][q * 2]     = hp0;
            Bhi[row][q * 2 + 1] = hp1;
            Blo[row][q * 2]     = pack_bf16x2(lx, ly);
            Blo[row][q * 2 + 1] = pack_bf16x2(lz, lw);
        }
        __syncthreads();

#pragma unroll
        for (int ks = 0; ks < 16; ks += 8) {
            unsigned ah[2][4], al[2][4], bh[2][4], bl[2][4];
#pragma unroll
            for (int mi = 0; mi < 2; mi++) {
                uint32_t off = (uint32_t)(((wm * 32 + mi * 16 + a_row) * GPAD + ks + a_col) << 2);
                LDSM4(ah[mi], sAhi + off);
                LDSM4(al[mi], sAlo + off);
            }
#pragma unroll
            for (int p = 0; p < 2; p++) {
                uint32_t off = (uint32_t)(((wn * 32 + p * 16 + b_row) * GPAD + ks + b_col) << 2);
                LDSM4(bh[p], sBhi + off);
                LDSM4(bl[p], sBlo + off);
            }
#pragma unroll
            for (int mi = 0; mi < 2; mi++)
#pragma unroll
                for (int ni = 0; ni < 4; ni++) {
                    int p = ni >> 1, o = (ni & 1) * 2;
                    MMA_BF16(acc[mi][ni], ah[mi], (&bh[p][o]));
                    MMA_BF16(acc[mi][ni], ah[mi], (&bl[p][o]));
                    MMA_BF16(acc[mi][ni], al[mi], (&bh[p][o]));
                }
        }
        __syncthreads();
    }

#pragma unroll
    for (int mi = 0; mi < 2; mi++)
#pragma unroll
        for (int ni = 0; ni < 4; ni++) {
            int r0 = bm + wm * 32 + mi * 16 + grp;
            int c0 = bn + wn * 32 + ni * 8 + tig * 2;
            if (r0 < NN)
                *(__half2*)&H[(size_t)r0 * D + c0] = __floats2half2_rn(acc[mi][ni][0], acc[mi][ni][1]);
            if (r0 + 8 < NN)
                *(__half2*)&H[(size_t)(r0 + 8) * D + c0] = __floats2half2_rn(acc[mi][ni][2], acc[mi][ni][3]);
        }
}

// ---------------- fused gather + bias + BN-stats ----------------
__global__ __launch_bounds__(128) void k_gather_bn(const float* __restrict__ bias,
                                                   float* __restrict__ out) {
    const int d = threadIdx.x;
    const __half2* __restrict__ H2 = (const __half2*)g_h;
    const float2 bi = *(const float2*)&bias[2 * d];
    float s0 = 0.f, s1 = 0.f, q0 = 0.f, q1 = 0.f;

    for (int c = blockIdx.x; c < NN; c += gridDim.x) {
        const float dc = g_dinv[c];
        const int beg = g_off[c] + g_boff[c >> 8];
        const int end = (c + 1 < NN) ? g_off[c + 1] + g_boff[(c + 1) >> 8] : NE;

        float2 hs = __half22float2(H2[(size_t)c * 128 + d]);
        float a0 = hs.x * dc, a1 = hs.y * dc;

        int j = beg;
        for (; j + 3 < end; j += 4) {
            int r0 = __ldg(&g_src[j]);
            int r1 = __ldg(&g_src[j + 1]);
            int r2 = __ldg(&g_src[j + 2]);
            int r3 = __ldg(&g_src[j + 3]);
            float w0 = g_dinv[r0], w1 = g_dinv[r1], w2 = g_dinv[r2], w3 = g_dinv[r3];
            float2 v0 = __half22float2(H2[(size_t)r0 * 128 + d]);
            float2 v1 = __half22float2(H2[(size_t)r1 * 128 + d]);
            float2 v2 = __half22float2(H2[(size_t)r2 * 128 + d]);
            float2 v3 = __half22float2(H2[(size_t)r3 * 128 + d]);
            a0 = fmaf(v0.x, w0, a0); a1 = fmaf(v0.y, w0, a1);
            a0 = fmaf(v1.x, w1, a0); a1 = fmaf(v1.y, w1, a1);
            a0 = fmaf(v2.x, w2, a0); a1 = fmaf(v2.y, w2, a1);
            a0 = fmaf(v3.x, w3, a0); a1 = fmaf(v3.y, w3, a1);
        }
        for (; j < end; j++) {
            int r = __ldg(&g_src[j]);
            float w = g_dinv[r];
            float2 v = __half22float2(H2[(size_t)r * 128 + d]);
            a0 = fmaf(v.x, w, a0); a1 = fmaf(v.y, w, a1);
        }
        float o0 = fmaf(a0, dc, bi.x);
        float o1 = fmaf(a1, dc, bi.y);
        *(float2*)&out[(size_t)c * D + 2 * d] = make_float2(o0, o1);
        s0 += o0; s1 += o1;
        q0 = fmaf(o0, o0, q0); q1 = fmaf(o1, o1, q1);
    }
    atomicAdd(&g_bnstat[2 * d], s0);
    atomicAdd(&g_bnstat[2 * d + 1], s1);
    atomicAdd(&g_bnstat[D + 2 * d], q0);
    atomicAdd(&g_bnstat[D + 2 * d + 1], q1);
}

// ---------------- BN finalize ----------------
__global__ void k_bn_params(const float* __restrict__ gamma, const float* __restrict__ beta) {
    int d = threadIdx.x;
    float inv_n = 1.0f / (float)NN;
    float mean = g_bnstat[d] * inv_n;
    float var = g_bnstat[D + d] * inv_n - mean * mean;
    float a = gamma[d] * rsqrtf(var + BN_EPS);
    g_bn_a[d] = a;
    g_bn_b[d] = beta[d] - mean * a;
}

__global__ void k_bn_apply(float* __restrict__ out) {
    int idx = blockIdx.x * blockDim.x + threadIdx.x;
    if (idx >= NN * (D / 4)) return;
    int dq = (idx & 63) * 4;
    float4 a = *(const float4*)&g_bn_a[dq];
    float4 b = *(const float4*)&g_bn_b[dq];
    float4 v = ((const float4*)out)[idx];
    float4 o;
    o.x = fmaxf(fmaf(v.x, a.x, b.x), 0.f);
    o.y = fmaxf(fmaf(v.y, a.y, b.y), 0.f);
    o.z = fmaxf(fmaf(v.z, a.z, b.z), 0.f);
    o.w = fmaxf(fmaf(v.w, a.w, b.w), 0.f);
    ((float4*)out)[idx] = o;
}

// ---------------- launch ----------------
extern "C" void kernel_launch(void* const* d_in, const int* in_sizes, int n_in,
                              void* d_out, int out_size) {
    const float* x = (const float*)d_in[0];
    const int* ei = (const int*)d_in[1];
    const float* W = (const float*)d_in[2];
    const float* bias = (const float*)d_in[3];
    const float* gamma = (const float*)d_in[4];
    const float* beta = (const float*)d_in[5];
    float* out = (float*)d_out;

    __half* h;  cudaGetSymbolAddress((void**)&h, g_h);
    int* cnt;   cudaGetSymbolAddress((void**)&cnt, g_cnt);
    float* bns; cudaGetSymbolAddress((void**)&bns, g_bnstat);

    cudaMemsetAsync(cnt, 0, NN * sizeof(int));
    cudaMemsetAsync(bns, 0, 2 * D * sizeof(float));

    // order keeps k_gemm_bf16 in the profiler's capture slot (4th kernel)
    k_count<<<(NE + 255) / 256, 256>>>(ei);
    k_scan1<<<NSCB, 256>>>();
    k_scan2<<<1, 256>>>();

    dim3 ggrid((NN + 127) / 128, D / 64);
    k_gemm_bf16<<<ggrid, 256>>>(x, W, h);

    k_fill<<<(NE + 255) / 256, 256>>>(ei);

    k_gather_bn<<<1480, 128>>>(bias, out);

    k_bn_params<<<1, 256>>>(gamma, beta);

    int q = NN * (D / 4);
    k_bn_apply<<<(q + 255) / 256, 256>>>(out);
}